// round 9
// baseline (speedup 1.0000x reference)
#include <cuda_runtime.h>
#include <cuda_fp16.h>
#include <math.h>
#include <stdint.h>

#define DIMX   1024
#define NHEADS 16
#define HDIM   64
#define ROT    32
#define BATCH  4
#define SEQ    2048
#define MROWS  (BATCH*SEQ)   // 8192

// ---------------------------------------------------------------------------
// Scratch (device globals -- no allocation allowed in kernel_launch)
// ---------------------------------------------------------------------------
__device__ __half g_qh[MROWS*DIMX];            // fp16 copies of inputs
__device__ __half g_kh[MROWS*DIMX];
__device__ __half g_vh[MROWS*DIMX];
__device__ __half g_Wh[4][DIMX*DIMX];          // fp16 Wq,Wk,Wv,Wo
__device__ __half g_Q[BATCH*NHEADS*SEQ*HDIM];  // [B,H,L,D] (Q pre-scaled 1/8)
__device__ __half g_K[BATCH*NHEADS*SEQ*HDIM];
__device__ __half g_V[BATCH*NHEADS*SEQ*HDIM];
__device__ __half g_A[BATCH*SEQ*DIMX];         // attention out [B,L,DIM]
__device__ float2 g_rope[SEQ * (ROT/2)];       // per-(l, pair) {cos, sin}

// ---------------------------------------------------------------------------
// helpers
// ---------------------------------------------------------------------------
__device__ __forceinline__ void mma16(float* c,
                                      uint32_t a0, uint32_t a1, uint32_t a2, uint32_t a3,
                                      uint32_t b0, uint32_t b1) {
    asm volatile(
        "mma.sync.aligned.m16n8k16.row.col.f32.f16.f16.f32 "
        "{%0,%1,%2,%3},{%4,%5,%6,%7},{%8,%9},{%0,%1,%2,%3};\n"
        : "+f"(c[0]), "+f"(c[1]), "+f"(c[2]), "+f"(c[3])
        : "r"(a0), "r"(a1), "r"(a2), "r"(a3), "r"(b0), "r"(b1));
}

__device__ __forceinline__ void ldm4(uint32_t* r, uint32_t addr) {
    asm volatile("ldmatrix.sync.aligned.m8n8.x4.shared.b16 {%0,%1,%2,%3}, [%4];"
                 : "=r"(r[0]), "=r"(r[1]), "=r"(r[2]), "=r"(r[3]) : "r"(addr));
}
__device__ __forceinline__ void ldm4t(uint32_t* r, uint32_t addr) {
    asm volatile("ldmatrix.sync.aligned.m8n8.x4.trans.shared.b16 {%0,%1,%2,%3}, [%4];"
                 : "=r"(r[0]), "=r"(r[1]), "=r"(r[2]), "=r"(r[3]) : "r"(addr));
}

__device__ __forceinline__ uint32_t smem_u32(const void* p) {
    uint32_t a;
    asm("{ .reg .u64 t; cvta.to.shared.u64 t, %1; cvt.u32.u64 %0, t; }"
        : "=r"(a) : "l"(p));
    return a;
}

__device__ __forceinline__ void cpa16(uint32_t dst, const void* src) {
    asm volatile("cp.async.cg.shared.global [%0], [%1], 16;"
                 :: "r"(dst), "l"(src) : "memory");
}
#define CP_COMMIT() asm volatile("cp.async.commit_group;" ::: "memory")
#define CP_WAIT(N)  asm volatile("cp.async.wait_group %0;" :: "n"(N) : "memory")

__device__ __forceinline__ uint32_t h2u(__half2 h) {
    return *reinterpret_cast<uint32_t*>(&h);
}

// ---------------------------------------------------------------------------
// one-shot staging kernels
// ---------------------------------------------------------------------------
__global__ void cvt3(const float* __restrict__ a, const float* __restrict__ b,
                     const float* __restrict__ c, __half* __restrict__ da,
                     __half* __restrict__ db, __half* __restrict__ dc, int n4)
{
    const float* s = blockIdx.y == 0 ? a : (blockIdx.y == 1 ? b : c);
    __half* d      = blockIdx.y == 0 ? da : (blockIdx.y == 1 ? db : dc);
    int i = blockIdx.x * blockDim.x + threadIdx.x;
    if (i < n4) {
        float4 v = reinterpret_cast<const float4*>(s)[i];
        uint2 u;
        u.x = h2u(__floats2half2_rn(v.x, v.y));
        u.y = h2u(__floats2half2_rn(v.z, v.w));
        reinterpret_cast<uint2*>(d)[i] = u;
    }
}

__global__ void cvt4(const float* __restrict__ a, const float* __restrict__ b,
                     const float* __restrict__ c, const float* __restrict__ e,
                     __half* __restrict__ dst, int n4)
{
    const float* s = blockIdx.y == 0 ? a : (blockIdx.y == 1 ? b
                    : (blockIdx.y == 2 ? c : e));
    __half* d = dst + (size_t)blockIdx.y * DIMX * DIMX;
    int i = blockIdx.x * blockDim.x + threadIdx.x;
    if (i < n4) {
        float4 v = reinterpret_cast<const float4*>(s)[i];
        uint2 u;
        u.x = h2u(__floats2half2_rn(v.x, v.y));
        u.y = h2u(__floats2half2_rn(v.z, v.w));
        reinterpret_cast<uint2*>(d)[i] = u;
    }
}

__global__ void ropetab(float2* __restrict__ tab)
{
    int i = blockIdx.x * blockDim.x + threadIdx.x;   // SEQ*16 entries
    if (i < SEQ * (ROT/2)) {
        int l = i >> 4;
        int p = i & 15;                               // pair index, d = 2p
        float invf = exp10f(-0.25f * (float)p);       // 10^(-d/8), d=2p
        float ang  = (float)l * invf;
        float sa, ca;
        sincosf(ang, &sa, &ca);
        tab[i] = make_float2(ca, sa);
    }
}

// ---------------------------------------------------------------------------
// GEMM core: 128x128x64 tile, 8 warps (4x2), warp 32x64, m16n8k16,
// 3-stage cp.async pipeline, ONE barrier per chunk.
// ---------------------------------------------------------------------------
#define GPAD    72
#define GSTG_H  (2 * 128 * GPAD)          // halfs per stage (A + W)
#define NSTG    3
#define GSMEM_B (NSTG * GSTG_H * 2)       // 110,592 B

struct GemmCore {
    uint32_t sbase, aoff, boff;
    int tid, m0, n0;
    const __half* A;
    const __half* W;

    __device__ __forceinline__ void load_chunk(int kt, int s) {
        uint32_t dst = sbase + (uint32_t)(s * GSTG_H * 2);
        #pragma unroll
        for (int it = 0; it < 4; it++) {
            int idx = tid + it * 256;        // 0..1023 16B slots
            int row = idx >> 3;
            int c   = idx & 7;
            cpa16(dst + (uint32_t)((row * GPAD + c * 8) * 2),
                  A + (size_t)(m0 + row) * DIMX + kt + c * 8);
            cpa16(dst + (uint32_t)((128 * GPAD + row * GPAD + c * 8) * 2),
                  W + (size_t)(n0 + row) * DIMX + kt + c * 8);
        }
        CP_COMMIT();
    }

    __device__ __forceinline__ void compute(int t, float acc[2][8][4]) {
        const uint32_t sb = sbase + (uint32_t)((t % NSTG) * GSTG_H * 2);
        #pragma unroll
        for (int kk = 0; kk < 4; kk++) {
            uint32_t a[2][4];
            ldm4(a[0], sb + aoff + kk * 32);
            ldm4(a[1], sb + aoff + 16 * GPAD * 2 + kk * 32);
            #pragma unroll
            for (int p = 0; p < 4; p++) {
                uint32_t b[4];
                ldm4(b, sb + boff + p * 16 * GPAD * 2 + kk * 32);
                mma16(acc[0][2*p],   a[0][0], a[0][1], a[0][2], a[0][3], b[0], b[1]);
                mma16(acc[0][2*p+1], a[0][0], a[0][1], a[0][2], a[0][3], b[2], b[3]);
                mma16(acc[1][2*p],   a[1][0], a[1][1], a[1][2], a[1][3], b[0], b[1]);
                mma16(acc[1][2*p+1], a[1][0], a[1][1], a[1][2], a[1][3], b[2], b[3]);
            }
        }
    }

    // 3 buffers, 2-ahead lookahead, single barrier per chunk.
    __device__ __forceinline__ void run(float acc[2][8][4]) {
        load_chunk(0, 0);
        load_chunk(64, 1);
        CP_WAIT(1);               // stage 0 ready
        __syncthreads();
        for (int t = 0; t < 16; t++) {
            if (t < 14) load_chunk((t + 2) * 64, (t + 2) % NSTG);
            compute(t, acc);
            if (t < 15) {
                if (t < 14) { CP_WAIT(1); } else { CP_WAIT(0); }
                __syncthreads();  // one barrier: next stage ready AND buffer t-1 free
            }
        }
    }
};

__device__ __forceinline__ void gemm_core_init(GemmCore& gc, const __half* A,
                                               const __half* W, void* sh)
{
    const int tid   = threadIdx.x;
    const int lane  = tid & 31;
    const int wid   = tid >> 5;
    const int rowin = lane & 7;
    const int sel   = lane >> 3;
    gc.tid   = tid;
    gc.m0    = blockIdx.y * 128;
    gc.n0    = blockIdx.x * 128;
    gc.A     = A;
    gc.W     = W;
    gc.sbase = smem_u32(sh);
    gc.aoff  = (uint32_t)((((wid >> 1) * 32 + ((sel & 1) << 3) + rowin) * GPAD
                           + ((sel >> 1) << 3)) * 2);
    gc.boff  = (uint32_t)((128 * GPAD
                           + ((wid & 1) * 64 + (((sel >> 1) & 1) << 3) + rowin) * GPAD
                           + ((sel & 1) << 3)) * 2);
}

// ---------------------------------------------------------------------------
// Merged projection GEMM: z=0 Q(+RoPE, *1/8), z=1 K(+RoPE), z=2 V.
// RoPE via precomputed cos/sin table. out is half in [B,H,L,D].
// ---------------------------------------------------------------------------
__global__ __launch_bounds__(256, 2)
void proj_h(const __half* __restrict__ qh, const __half* __restrict__ kh,
            const __half* __restrict__ vh, const __half* __restrict__ Wh,
            const float* __restrict__ bq, const float* __restrict__ bk,
            const float* __restrict__ bv, const float2* __restrict__ rope,
            __half* __restrict__ pQ, __half* __restrict__ pK, __half* __restrict__ pV)
{
    extern __shared__ __half sh[];
    const int z = blockIdx.z;
    const __half* A    = z == 0 ? qh : (z == 1 ? kh : vh);
    const __half* W    = Wh + (size_t)z * DIMX * DIMX;
    const float*  bias = z == 0 ? bq : (z == 1 ? bk : bv);
    __half*       out  = z == 0 ? pQ : (z == 1 ? pK : pV);
    const bool  rpe    = (z < 2);
    const float oscale = (z == 0) ? 0.125f : 1.0f;

    GemmCore gc;
    gemm_core_init(gc, A, W, sh);

    float acc[2][8][4];
    #pragma unroll
    for (int mt = 0; mt < 2; mt++)
        #pragma unroll
        for (int nt = 0; nt < 8; nt++)
            #pragma unroll
            for (int i = 0; i < 4; i++) acc[mt][nt][i] = 0.f;

    gc.run(acc);

    const int lane = threadIdx.x & 31;
    const int wid  = threadIdx.x >> 5;
    const int g    = lane >> 2;
    const int t4   = lane & 3;

    #pragma unroll
    for (int mt = 0; mt < 2; mt++) {
        #pragma unroll
        for (int nt = 0; nt < 8; nt++) {
            int r   = gc.m0 + (wid >> 1) * 32 + mt * 16 + g;
            int col = gc.n0 + (wid & 1) * 64 + nt * 8 + 2 * t4;
            float b0 = bias[col], b1 = bias[col + 1];
            float x00 = acc[mt][nt][0] + b0, x01 = acc[mt][nt][1] + b1;
            float x10 = acc[mt][nt][2] + b0, x11 = acc[mt][nt][3] + b1;
            int hh = col >> 6;
            int d  = col & 63;
            #pragma unroll
            for (int rr = 0; rr < 2; rr++) {
                int m  = r + rr * 8;
                int bb = m >> 11;
                int l  = m & (SEQ - 1);
                float y0 = rr ? x10 : x00;
                float y1 = rr ? x11 : x01;
                if (rpe && d < ROT) {
                    float2 cs = rope[l * (ROT/2) + (d >> 1)];
                    float z0 = y0 * cs.x - y1 * cs.y;
                    float z1 = y1 * cs.x + y0 * cs.y;
                    y0 = z0; y1 = z1;
                }
                size_t o = ((size_t)(bb * NHEADS + hh) * SEQ + l) * HDIM + d;
                *reinterpret_cast<__half2*>(out + o) =
                    __floats2half2_rn(y0 * oscale, y1 * oscale);
            }
        }
    }
}

// ---------------------------------------------------------------------------
// Output projection GEMM: fp32 row-major out.
// ---------------------------------------------------------------------------
__global__ __launch_bounds__(256, 2)
void gemmo_h(const __half* __restrict__ A, const __half* __restrict__ W,
             const float* __restrict__ bias, float* __restrict__ out)
{
    extern __shared__ __half sh[];
    GemmCore gc;
    gemm_core_init(gc, A, W, sh);

    float acc[2][8][4];
    #pragma unroll
    for (int mt = 0; mt < 2; mt++)
        #pragma unroll
        for (int nt = 0; nt < 8; nt++)
            #pragma unroll
            for (int i = 0; i < 4; i++) acc[mt][nt][i] = 0.f;

    gc.run(acc);

    const int lane = threadIdx.x & 31;
    const int wid  = threadIdx.x >> 5;
    const int g    = lane >> 2;
    const int t4   = lane & 3;

    #pragma unroll
    for (int mt = 0; mt < 2; mt++) {
        #pragma unroll
        for (int nt = 0; nt < 8; nt++) {
            int r   = gc.m0 + (wid >> 1) * 32 + mt * 16 + g;
            int col = gc.n0 + (wid & 1) * 64 + nt * 8 + 2 * t4;
            float b0 = bias[col], b1 = bias[col + 1];
            *reinterpret_cast<float2*>(out + (size_t)r * DIMX + col) =
                make_float2(acc[mt][nt][0] + b0, acc[mt][nt][1] + b1);
            *reinterpret_cast<float2*>(out + (size_t)(r + 8) * DIMX + col) =
                make_float2(acc[mt][nt][2] + b0, acc[mt][nt][3] + b1);
        }
    }
}

// ---------------------------------------------------------------------------
// fp16 flash attention: 3-stage cp.async KV pipeline (one barrier/chunk),
// static softmax, V via ldmatrix.trans. BQ=128, BK=64, 8 warps.
// Q arrives pre-scaled by 1/8.
// ---------------------------------------------------------------------------
#define FPAD     72
#define FQ_H     (128 * FPAD)
#define FKV_H    (64 * FPAD)
#define FSTG_H   (2 * FKV_H)
#define FNSTG    3
#define FSMEM_B  ((FQ_H + FNSTG * FSTG_H) * 2)   // 73,728 B

__global__ __launch_bounds__(256, 2)
void flash_h(const __half* __restrict__ Q, const __half* __restrict__ K,
             const __half* __restrict__ V, __half* __restrict__ Out)
{
    extern __shared__ __half sh[];

    const int tid   = threadIdx.x;
    const int lane  = tid & 31;
    const int wid   = tid >> 5;
    const int g     = lane >> 2;
    const int t4    = lane & 3;
    const int q0    = blockIdx.x * 128;
    const int h     = blockIdx.y;
    const int bb    = blockIdx.z;
    const int rowin = lane & 7;
    const int sel   = lane >> 3;

    const __half* Qb = Q + ((size_t)(bb * NHEADS + h) * SEQ + q0) * HDIM;
    const __half* Kb = K + (size_t)(bb * NHEADS + h) * SEQ * HDIM;
    const __half* Vb = V + (size_t)(bb * NHEADS + h) * SEQ * HDIM;

    const uint32_t sbase = smem_u32(sh);

    auto load_kv = [&](int k0, int s) {
        uint32_t kdst = sbase + (uint32_t)((FQ_H + s * FSTG_H) * 2);
        uint32_t vdst = kdst + (uint32_t)(FKV_H * 2);
        #pragma unroll
        for (int it = 0; it < 2; it++) {
            int idx = tid + it * 256;        // 0..511 16B slots
            int row = idx >> 3;
            int c   = idx & 7;
            cpa16(kdst + (uint32_t)((row * FPAD + c * 8) * 2),
                  Kb + (size_t)(k0 + row) * HDIM + c * 8);
            cpa16(vdst + (uint32_t)((row * FPAD + c * 8) * 2),
                  Vb + (size_t)(k0 + row) * HDIM + c * 8);
        }
        CP_COMMIT();
    };

    // Prologue: {Q + kv0} group, then kv1 group.
    #pragma unroll
    for (int it = 0; it < 4; it++) {
        int idx = tid + it * 256;            // 0..1023
        int row = idx >> 3;
        int c   = idx & 7;
        cpa16(sbase + (uint32_t)((row * FPAD + c * 8) * 2),
              Qb + (size_t)row * HDIM + c * 8);
    }
    {
        uint32_t kdst = sbase + (uint32_t)(FQ_H * 2);
        uint32_t vdst = kdst + (uint32_t)(FKV_H * 2);
        #pragma unroll
        for (int it = 0; it < 2; it++) {
            int idx = tid + it * 256;
            int row = idx >> 3;
            int c   = idx & 7;
            cpa16(kdst + (uint32_t)((row * FPAD + c * 8) * 2),
                  Kb + (size_t)row * HDIM + c * 8);
            cpa16(vdst + (uint32_t)((row * FPAD + c * 8) * 2),
                  Vb + (size_t)row * HDIM + c * 8);
        }
        CP_COMMIT();
    }
    load_kv(64, 1);
    CP_WAIT(1);          // Q + kv0 ready
    __syncthreads();

    uint32_t qf[4][4];
    {
        const uint32_t qbase = sbase +
            (uint32_t)(((wid * 16 + ((sel & 1) << 3) + rowin) * FPAD
                        + ((sel >> 1) << 3)) * 2);
        #pragma unroll
        for (int kk = 0; kk < 4; kk++) ldm4(qf[kk], qbase + kk * 32);
    }

    const int krow = ((((sel >> 1) & 1)) << 3) + rowin;
    const int kcol = (sel & 1) << 3;
    const int vrow = ((sel & 1) << 3) + rowin;
    const int vcol = (sel >> 1) << 3;

    float l0 = 0.f, l1 = 0.f;
    float oacc[8][4];
    #pragma unroll
    for (int nt = 0; nt < 8; nt++)
        #pragma unroll
        for (int i = 0; i < 4; i++) oacc[nt][i] = 0.f;

    const int NC = SEQ / 64;   // 32 chunks
    for (int c = 0; c < NC; c++) {
        if (c < NC - 2) load_kv((c + 2) * 64, (c + 2) % FNSTG);

        const uint32_t kbs = sbase + (uint32_t)((FQ_H + (c % FNSTG) * FSTG_H) * 2);
        const uint32_t vbs = kbs + (uint32_t)(FKV_H * 2);

        // S = Q K^T
        float sa[8][4];
        #pragma unroll
        for (int nt = 0; nt < 8; nt++)
            #pragma unroll
            for (int i = 0; i < 4; i++) sa[nt][i] = 0.f;
        #pragma unroll
        for (int kk = 0; kk < 4; kk++) {
            #pragma unroll
            for (int p = 0; p < 4; p++) {
                uint32_t b[4];
                ldm4(b, kbs + (uint32_t)((((p * 16 + krow) * FPAD)
                                          + kcol + kk * 16) * 2));
                mma16(sa[2*p],   qf[kk][0], qf[kk][1], qf[kk][2], qf[kk][3], b[0], b[1]);
                mma16(sa[2*p+1], qf[kk][0], qf[kk][1], qf[kk][2], qf[kk][3], b[2], b[3]);
            }
        }

        // Static softmax: P = exp(S), sums of fp16-rounded P
        uint32_t pf[8][2];
        float s0 = 0.f, s1 = 0.f;
        #pragma unroll
        for (int nt = 0; nt < 8; nt++) {
            __half2 h01 = __floats2half2_rn(__expf(sa[nt][0]), __expf(sa[nt][1]));
            __half2 h23 = __floats2half2_rn(__expf(sa[nt][2]), __expf(sa[nt][3]));
            pf[nt][0] = h2u(h01);
            pf[nt][1] = h2u(h23);
            float2 f01 = __half22float2(h01);
            float2 f23 = __half22float2(h23);
            s0 += f01.x + f01.y;
            s1 += f23.x + f23.y;
        }
        s0 += __shfl_xor_sync(0xffffffffu, s0, 1);
        s0 += __shfl_xor_sync(0xffffffffu, s0, 2);
        s1 += __shfl_xor_sync(0xffffffffu, s1, 1);
        s1 += __shfl_xor_sync(0xffffffffu, s1, 2);
        l0 += s0;
        l1 += s1;

        // PV: O += P @ V
        #pragma unroll
        for (int j = 0; j < 4; j++) {
            uint32_t a0 = pf[2 * j][0];
            uint32_t a1 = pf[2 * j][1];
            uint32_t a2 = pf[2 * j + 1][0];
            uint32_t a3 = pf[2 * j + 1][1];
            #pragma unroll
            for (int p = 0; p < 4; p++) {
                uint32_t b[4];
                ldm4t(b, vbs + (uint32_t)((((j * 16 + vrow) * FPAD)
                                           + p * 16 + vcol) * 2));
                mma16(oacc[2*p],   a0, a1, a2, a3, b[0], b[1]);
                mma16(oacc[2*p+1], a0, a1, a2, a3, b[2], b[3]);
            }
        }

        if (c < NC - 1) {
            if (c < NC - 2) { CP_WAIT(1); } else { CP_WAIT(0); }
            __syncthreads();   // next stage ready AND buffer c-1 free
        }
    }

    float i0 = 1.f / l0;
    float i1 = 1.f / l1;
    size_t rbase0 = ((size_t)(bb * SEQ + q0 + wid * 16 + g))     * DIMX + h * HDIM;
    size_t rbase1 = ((size_t)(bb * SEQ + q0 + wid * 16 + g + 8)) * DIMX + h * HDIM;
    #pragma unroll
    for (int nt = 0; nt < 8; nt++) {
        int d = nt * 8 + 2 * t4;
        *reinterpret_cast<__half2*>(Out + rbase0 + d) =
            __floats2half2_rn(oacc[nt][0] * i0, oacc[nt][1] * i0);
        *reinterpret_cast<__half2*>(Out + rbase1 + d) =
            __floats2half2_rn(oacc[nt][2] * i1, oacc[nt][3] * i1);
    }
}

// ---------------------------------------------------------------------------
// Launch
// ---------------------------------------------------------------------------
extern "C" void kernel_launch(void* const* d_in, const int* in_sizes, int n_in,
                              void* d_out, int out_size)
{
    const float* q  = (const float*)d_in[0];
    const float* k  = (const float*)d_in[1];
    const float* v  = (const float*)d_in[2];
    const float* Wq = (const float*)d_in[3];
    const float* bq = (const float*)d_in[4];
    const float* Wk = (const float*)d_in[5];
    const float* bk = (const float*)d_in[6];
    const float* Wv = (const float*)d_in[7];
    const float* bv = (const float*)d_in[8];
    const float* Wo = (const float*)d_in[9];
    const float* bo = (const float*)d_in[10];
    float* out = (float*)d_out;

    __half *qh, *kh, *vh, *Wh, *pQ, *pK, *pV, *pA;
    float2* rope;
    cudaGetSymbolAddress((void**)&qh, g_qh);
    cudaGetSymbolAddress((void**)&kh, g_kh);
    cudaGetSymbolAddress((void**)&vh, g_vh);
    cudaGetSymbolAddress((void**)&Wh, g_Wh);
    cudaGetSymbolAddress((void**)&pQ, g_Q);
    cudaGetSymbolAddress((void**)&pK, g_K);
    cudaGetSymbolAddress((void**)&pV, g_V);
    cudaGetSymbolAddress((void**)&pA, g_A);
    cudaGetSymbolAddress((void**)&rope, g_rope);

    cudaFuncSetAttribute(proj_h,  cudaFuncAttributeMaxDynamicSharedMemorySize, GSMEM_B);
    cudaFuncSetAttribute(gemmo_h, cudaFuncAttributeMaxDynamicSharedMemorySize, GSMEM_B);
    cudaFuncSetAttribute(flash_h, cudaFuncAttributeMaxDynamicSharedMemorySize, FSMEM_B);

    // staging: fp16 copies + RoPE table
    cvt3<<<dim3(MROWS*DIMX/4/256, 3), 256>>>(q, k, v, qh, kh, vh, MROWS*DIMX/4);
    cvt4<<<dim3(DIMX*DIMX/4/256, 4), 256>>>(Wq, Wk, Wv, Wo, Wh, DIMX*DIMX/4);
    ropetab<<<SEQ*(ROT/2)/256, 256>>>(rope);

    proj_h<<<dim3(DIMX/128, MROWS/128, 3), 256, GSMEM_B>>>(
        qh, kh, vh, Wh, bq, bk, bv, rope, pQ, pK, pV);

    flash_h<<<dim3(SEQ/128, NHEADS, BATCH), 256, FSMEM_B>>>(pQ, pK, pV, pA);

    gemmo_h<<<dim3(DIMX/128, MROWS/128), 256, GSMEM_B>>>(
        pA, Wh + 3*DIMX*DIMX, bo, out);
}

// round 10
// speedup vs baseline: 1.0167x; 1.0167x over previous
#include <cuda_runtime.h>
#include <cuda_fp16.h>
#include <math.h>
#include <stdint.h>

#define DIMX   1024
#define NHEADS 16
#define HDIM   64
#define ROT    32
#define BATCH  4
#define SEQ    2048
#define MROWS  (BATCH*SEQ)   // 8192

// ---------------------------------------------------------------------------
// Scratch (device globals -- no allocation allowed in kernel_launch)
// ---------------------------------------------------------------------------
__device__ __half g_qh[MROWS*DIMX];            // fp16 copies of inputs
__device__ __half g_kh[MROWS*DIMX];
__device__ __half g_vh[MROWS*DIMX];
__device__ __half g_Wh[4][DIMX*DIMX];          // fp16 Wq,Wk,Wv,Wo
__device__ __half g_Q[BATCH*NHEADS*SEQ*HDIM];  // [B,H,L,D] (Q pre-scaled 1/8)
__device__ __half g_K[BATCH*NHEADS*SEQ*HDIM];
__device__ __half g_V[BATCH*NHEADS*SEQ*HDIM];
__device__ __half g_A[BATCH*SEQ*DIMX];         // attention out [B,L,DIM]
__device__ float2 g_rope[SEQ * (ROT/2)];       // per-(l, pair) {cos, sin}

// ---------------------------------------------------------------------------
// helpers
// ---------------------------------------------------------------------------
__device__ __forceinline__ void mma16(float* c,
                                      uint32_t a0, uint32_t a1, uint32_t a2, uint32_t a3,
                                      uint32_t b0, uint32_t b1) {
    asm volatile(
        "mma.sync.aligned.m16n8k16.row.col.f32.f16.f16.f32 "
        "{%0,%1,%2,%3},{%4,%5,%6,%7},{%8,%9},{%0,%1,%2,%3};\n"
        : "+f"(c[0]), "+f"(c[1]), "+f"(c[2]), "+f"(c[3])
        : "r"(a0), "r"(a1), "r"(a2), "r"(a3), "r"(b0), "r"(b1));
}

__device__ __forceinline__ void ldm4(uint32_t* r, uint32_t addr) {
    asm volatile("ldmatrix.sync.aligned.m8n8.x4.shared.b16 {%0,%1,%2,%3}, [%4];"
                 : "=r"(r[0]), "=r"(r[1]), "=r"(r[2]), "=r"(r[3]) : "r"(addr));
}
__device__ __forceinline__ void ldm4t(uint32_t* r, uint32_t addr) {
    asm volatile("ldmatrix.sync.aligned.m8n8.x4.trans.shared.b16 {%0,%1,%2,%3}, [%4];"
                 : "=r"(r[0]), "=r"(r[1]), "=r"(r[2]), "=r"(r[3]) : "r"(addr));
}

__device__ __forceinline__ uint32_t smem_u32(const void* p) {
    uint32_t a;
    asm("{ .reg .u64 t; cvta.to.shared.u64 t, %1; cvt.u32.u64 %0, t; }"
        : "=r"(a) : "l"(p));
    return a;
}

__device__ __forceinline__ void cpa16(uint32_t dst, const void* src) {
    asm volatile("cp.async.cg.shared.global [%0], [%1], 16;"
                 :: "r"(dst), "l"(src) : "memory");
}
#define CP_COMMIT() asm volatile("cp.async.commit_group;" ::: "memory")
#define CP_WAIT(N)  asm volatile("cp.async.wait_group %0;" :: "n"(N) : "memory")

__device__ __forceinline__ uint32_t h2u(__half2 h) {
    return *reinterpret_cast<uint32_t*>(&h);
}

// ---------------------------------------------------------------------------
// one-shot staging kernels
// ---------------------------------------------------------------------------
__global__ void cvt3(const float* __restrict__ a, const float* __restrict__ b,
                     const float* __restrict__ c, __half* __restrict__ da,
                     __half* __restrict__ db, __half* __restrict__ dc, int n4)
{
    const float* s = blockIdx.y == 0 ? a : (blockIdx.y == 1 ? b : c);
    __half* d      = blockIdx.y == 0 ? da : (blockIdx.y == 1 ? db : dc);
    int i = blockIdx.x * blockDim.x + threadIdx.x;
    if (i < n4) {
        float4 v = reinterpret_cast<const float4*>(s)[i];
        uint2 u;
        u.x = h2u(__floats2half2_rn(v.x, v.y));
        u.y = h2u(__floats2half2_rn(v.z, v.w));
        reinterpret_cast<uint2*>(d)[i] = u;
    }
}

__global__ void cvt4(const float* __restrict__ a, const float* __restrict__ b,
                     const float* __restrict__ c, const float* __restrict__ e,
                     __half* __restrict__ dst, int n4)
{
    const float* s = blockIdx.y == 0 ? a : (blockIdx.y == 1 ? b
                    : (blockIdx.y == 2 ? c : e));
    __half* d = dst + (size_t)blockIdx.y * DIMX * DIMX;
    int i = blockIdx.x * blockDim.x + threadIdx.x;
    if (i < n4) {
        float4 v = reinterpret_cast<const float4*>(s)[i];
        uint2 u;
        u.x = h2u(__floats2half2_rn(v.x, v.y));
        u.y = h2u(__floats2half2_rn(v.z, v.w));
        reinterpret_cast<uint2*>(d)[i] = u;
    }
}

__global__ void ropetab(float2* __restrict__ tab)
{
    int i = blockIdx.x * blockDim.x + threadIdx.x;   // SEQ*16 entries
    if (i < SEQ * (ROT/2)) {
        int l = i >> 4;
        int p = i & 15;                               // pair index, d = 2p
        float invf = exp10f(-0.25f * (float)p);       // 10^(-d/8), d=2p
        float ang  = (float)l * invf;
        float sa, ca;
        sincosf(ang, &sa, &ca);
        tab[i] = make_float2(ca, sa);
    }
}

// ---------------------------------------------------------------------------
// GEMM core: 128x128x64 CTA tile, 4 warps (2x2), warp tile 64x64, m16n8k16,
// 3-stage cp.async pipeline, one barrier per chunk.
// Per kk-step: 8 ldmatrix.x4 feed 32 mma (2x the old reuse).
// ---------------------------------------------------------------------------
#define GPAD    72
#define GSTG_H  (2 * 128 * GPAD)          // halfs per stage (A + W)
#define NSTG    3
#define GSMEM_B (NSTG * GSTG_H * 2)       // 110,592 B

struct GemmCore {
    uint32_t sbase, aoff, boff;
    int tid, m0, n0;
    const __half* A;
    const __half* W;

    __device__ __forceinline__ void load_chunk(int kt, int s) {
        uint32_t dst = sbase + (uint32_t)(s * GSTG_H * 2);
        #pragma unroll
        for (int it = 0; it < 8; it++) {
            int idx = tid + it * 128;        // 0..1023 16B slots
            int row = idx >> 3;
            int c   = idx & 7;
            cpa16(dst + (uint32_t)((row * GPAD + c * 8) * 2),
                  A + (size_t)(m0 + row) * DIMX + kt + c * 8);
            cpa16(dst + (uint32_t)((128 * GPAD + row * GPAD + c * 8) * 2),
                  W + (size_t)(n0 + row) * DIMX + kt + c * 8);
        }
        CP_COMMIT();
    }

    __device__ __forceinline__ void compute(int t, float acc[4][8][4]) {
        const uint32_t sb = sbase + (uint32_t)((t % NSTG) * GSTG_H * 2);
        #pragma unroll
        for (int kk = 0; kk < 4; kk++) {
            uint32_t a[4][4];
            #pragma unroll
            for (int mt = 0; mt < 4; mt++)
                ldm4(a[mt], sb + aoff + mt * 16 * GPAD * 2 + kk * 32);
            #pragma unroll
            for (int p = 0; p < 4; p++) {
                uint32_t b[4];
                ldm4(b, sb + boff + p * 16 * GPAD * 2 + kk * 32);
                #pragma unroll
                for (int mt = 0; mt < 4; mt++) {
                    mma16(acc[mt][2*p],   a[mt][0], a[mt][1], a[mt][2], a[mt][3], b[0], b[1]);
                    mma16(acc[mt][2*p+1], a[mt][0], a[mt][1], a[mt][2], a[mt][3], b[2], b[3]);
                }
            }
        }
    }

    __device__ __forceinline__ void run(float acc[4][8][4]) {
        load_chunk(0, 0);
        load_chunk(64, 1);
        CP_WAIT(1);
        __syncthreads();
        for (int t = 0; t < 16; t++) {
            if (t < 14) load_chunk((t + 2) * 64, (t + 2) % NSTG);
            compute(t, acc);
            if (t < 15) {
                if (t < 14) { CP_WAIT(1); } else { CP_WAIT(0); }
                __syncthreads();
            }
        }
    }
};

__device__ __forceinline__ void gemm_core_init(GemmCore& gc, const __half* A,
                                               const __half* W, void* sh)
{
    const int tid   = threadIdx.x;
    const int lane  = tid & 31;
    const int wid   = tid >> 5;        // 0..3
    const int rowin = lane & 7;
    const int sel   = lane >> 3;
    gc.tid   = tid;
    gc.m0    = blockIdx.y * 128;
    gc.n0    = blockIdx.x * 128;
    gc.A     = A;
    gc.W     = W;
    gc.sbase = smem_u32(sh);
    // warp (wid>>1, wid&1): rows (wid>>1)*64, cols (wid&1)*64
    gc.aoff  = (uint32_t)((((wid >> 1) * 64 + ((sel & 1) << 3) + rowin) * GPAD
                           + ((sel >> 1) << 3)) * 2);
    gc.boff  = (uint32_t)((128 * GPAD
                           + ((wid & 1) * 64 + (((sel >> 1) & 1) << 3) + rowin) * GPAD
                           + ((sel & 1) << 3)) * 2);
}

// ---------------------------------------------------------------------------
// Merged projection GEMM: z=0 Q(+RoPE, *1/8), z=1 K(+RoPE), z=2 V.
// ---------------------------------------------------------------------------
__global__ __launch_bounds__(128, 2)
void proj_h(const __half* __restrict__ qh, const __half* __restrict__ kh,
            const __half* __restrict__ vh, const __half* __restrict__ Wh,
            const float* __restrict__ bq, const float* __restrict__ bk,
            const float* __restrict__ bv, const float2* __restrict__ rope,
            __half* __restrict__ pQ, __half* __restrict__ pK, __half* __restrict__ pV)
{
    extern __shared__ __half sh[];
    const int z = blockIdx.z;
    const __half* A    = z == 0 ? qh : (z == 1 ? kh : vh);
    const __half* W    = Wh + (size_t)z * DIMX * DIMX;
    const float*  bias = z == 0 ? bq : (z == 1 ? bk : bv);
    __half*       out  = z == 0 ? pQ : (z == 1 ? pK : pV);
    const bool  rpe    = (z < 2);
    const float oscale = (z == 0) ? 0.125f : 1.0f;

    GemmCore gc;
    gemm_core_init(gc, A, W, sh);

    float acc[4][8][4];
    #pragma unroll
    for (int mt = 0; mt < 4; mt++)
        #pragma unroll
        for (int nt = 0; nt < 8; nt++)
            #pragma unroll
            for (int i = 0; i < 4; i++) acc[mt][nt][i] = 0.f;

    gc.run(acc);

    const int lane = threadIdx.x & 31;
    const int wid  = threadIdx.x >> 5;
    const int g    = lane >> 2;
    const int t4   = lane & 3;

    #pragma unroll
    for (int mt = 0; mt < 4; mt++) {
        #pragma unroll
        for (int nt = 0; nt < 8; nt++) {
            int r   = gc.m0 + (wid >> 1) * 64 + mt * 16 + g;
            int col = gc.n0 + (wid & 1) * 64 + nt * 8 + 2 * t4;
            float b0 = bias[col], b1 = bias[col + 1];
            float x00 = acc[mt][nt][0] + b0, x01 = acc[mt][nt][1] + b1;
            float x10 = acc[mt][nt][2] + b0, x11 = acc[mt][nt][3] + b1;
            int hh = col >> 6;
            int d  = col & 63;
            #pragma unroll
            for (int rr = 0; rr < 2; rr++) {
                int m  = r + rr * 8;
                int bb = m >> 11;
                int l  = m & (SEQ - 1);
                float y0 = rr ? x10 : x00;
                float y1 = rr ? x11 : x01;
                if (rpe && d < ROT) {
                    float2 cs = rope[l * (ROT/2) + (d >> 1)];
                    float z0 = y0 * cs.x - y1 * cs.y;
                    float z1 = y1 * cs.x + y0 * cs.y;
                    y0 = z0; y1 = z1;
                }
                size_t o = ((size_t)(bb * NHEADS + hh) * SEQ + l) * HDIM + d;
                *reinterpret_cast<__half2*>(out + o) =
                    __floats2half2_rn(y0 * oscale, y1 * oscale);
            }
        }
    }
}

// ---------------------------------------------------------------------------
// Output projection GEMM: fp32 row-major out.
// ---------------------------------------------------------------------------
__global__ __launch_bounds__(128, 2)
void gemmo_h(const __half* __restrict__ A, const __half* __restrict__ W,
             const float* __restrict__ bias, float* __restrict__ out)
{
    extern __shared__ __half sh[];
    GemmCore gc;
    gemm_core_init(gc, A, W, sh);

    float acc[4][8][4];
    #pragma unroll
    for (int mt = 0; mt < 4; mt++)
        #pragma unroll
        for (int nt = 0; nt < 8; nt++)
            #pragma unroll
            for (int i = 0; i < 4; i++) acc[mt][nt][i] = 0.f;

    gc.run(acc);

    const int lane = threadIdx.x & 31;
    const int wid  = threadIdx.x >> 5;
    const int g    = lane >> 2;
    const int t4   = lane & 3;

    #pragma unroll
    for (int mt = 0; mt < 4; mt++) {
        #pragma unroll
        for (int nt = 0; nt < 8; nt++) {
            int r   = gc.m0 + (wid >> 1) * 64 + mt * 16 + g;
            int col = gc.n0 + (wid & 1) * 64 + nt * 8 + 2 * t4;
            float b0 = bias[col], b1 = bias[col + 1];
            *reinterpret_cast<float2*>(out + (size_t)r * DIMX + col) =
                make_float2(acc[mt][nt][0] + b0, acc[mt][nt][1] + b1);
            *reinterpret_cast<float2*>(out + (size_t)(r + 8) * DIMX + col) =
                make_float2(acc[mt][nt][2] + b0, acc[mt][nt][3] + b1);
        }
    }
}

// ---------------------------------------------------------------------------
// fp16 flash attention: 4 warps x 32 q-rows (BQ=128), BK=64, static softmax,
// 3-stage cp.async KV pipeline, Q and P register-resident (no A-side LDSM).
// Q arrives pre-scaled by 1/8.
// ---------------------------------------------------------------------------
#define FPAD     72
#define FQ_H     (128 * FPAD)
#define FKV_H    (64 * FPAD)
#define FSTG_H   (2 * FKV_H)
#define FNSTG    3
#define FSMEM_B  ((FQ_H + FNSTG * FSTG_H) * 2)   // 73,728 B

__global__ __launch_bounds__(128, 2)
void flash_h(const __half* __restrict__ Q, const __half* __restrict__ K,
             const __half* __restrict__ V, __half* __restrict__ Out)
{
    extern __shared__ __half sh[];

    const int tid   = threadIdx.x;
    const int lane  = tid & 31;
    const int wid   = tid >> 5;        // 0..3, q-rows [32w, 32w+32)
    const int g     = lane >> 2;
    const int t4    = lane & 3;
    const int q0    = blockIdx.x * 128;
    const int h     = blockIdx.y;
    const int bb    = blockIdx.z;
    const int rowin = lane & 7;
    const int sel   = lane >> 3;

    const __half* Qb = Q + ((size_t)(bb * NHEADS + h) * SEQ + q0) * HDIM;
    const __half* Kb = K + (size_t)(bb * NHEADS + h) * SEQ * HDIM;
    const __half* Vb = V + (size_t)(bb * NHEADS + h) * SEQ * HDIM;

    const uint32_t sbase = smem_u32(sh);

    auto load_kv = [&](int k0, int s) {
        uint32_t kdst = sbase + (uint32_t)((FQ_H + s * FSTG_H) * 2);
        uint32_t vdst = kdst + (uint32_t)(FKV_H * 2);
        #pragma unroll
        for (int it = 0; it < 4; it++) {
            int idx = tid + it * 128;        // 0..511 16B slots
            int row = idx >> 3;
            int c   = idx & 7;
            cpa16(kdst + (uint32_t)((row * FPAD + c * 8) * 2),
                  Kb + (size_t)(k0 + row) * HDIM + c * 8);
            cpa16(vdst + (uint32_t)((row * FPAD + c * 8) * 2),
                  Vb + (size_t)(k0 + row) * HDIM + c * 8);
        }
        CP_COMMIT();
    };

    // Prologue: {Q + kv0} group, then kv1 group.
    #pragma unroll
    for (int it = 0; it < 8; it++) {
        int idx = tid + it * 128;            // 0..1023
        int row = idx >> 3;
        int c   = idx & 7;
        cpa16(sbase + (uint32_t)((row * FPAD + c * 8) * 2),
              Qb + (size_t)row * HDIM + c * 8);
    }
    {
        uint32_t kdst = sbase + (uint32_t)(FQ_H * 2);
        uint32_t vdst = kdst + (uint32_t)(FKV_H * 2);
        #pragma unroll
        for (int it = 0; it < 4; it++) {
            int idx = tid + it * 128;
            int row = idx >> 3;
            int c   = idx & 7;
            cpa16(kdst + (uint32_t)((row * FPAD + c * 8) * 2),
                  Kb + (size_t)row * HDIM + c * 8);
            cpa16(vdst + (uint32_t)((row * FPAD + c * 8) * 2),
                  Vb + (size_t)row * HDIM + c * 8);
        }
        CP_COMMIT();
    }
    load_kv(64, 1);
    CP_WAIT(1);          // Q + kv0 ready
    __syncthreads();

    // Preload Q A-fragments for both 16-row tiles (loop-invariant)
    uint32_t qf[2][4][4];
    #pragma unroll
    for (int mt = 0; mt < 2; mt++) {
        const uint32_t qbase = sbase +
            (uint32_t)(((wid * 32 + mt * 16 + ((sel & 1) << 3) + rowin) * FPAD
                        + ((sel >> 1) << 3)) * 2);
        #pragma unroll
        for (int kk = 0; kk < 4; kk++) ldm4(qf[mt][kk], qbase + kk * 32);
    }

    const int krow = ((((sel >> 1) & 1)) << 3) + rowin;
    const int kcol = (sel & 1) << 3;
    const int vrow = ((sel & 1) << 3) + rowin;
    const int vcol = (sel >> 1) << 3;

    float lsum[2][2] = {{0.f, 0.f}, {0.f, 0.f}};
    float oacc[2][8][4];
    #pragma unroll
    for (int mt = 0; mt < 2; mt++)
        #pragma unroll
        for (int nt = 0; nt < 8; nt++)
            #pragma unroll
            for (int i = 0; i < 4; i++) oacc[mt][nt][i] = 0.f;

    const int NC = SEQ / 64;   // 32 chunks
    for (int c = 0; c < NC; c++) {
        if (c < NC - 2) load_kv((c + 2) * 64, (c + 2) % FNSTG);

        const uint32_t kbs = sbase + (uint32_t)((FQ_H + (c % FNSTG) * FSTG_H) * 2);
        const uint32_t vbs = kbs + (uint32_t)(FKV_H * 2);

        // S = Q K^T : warp's 32 q-rows x 64 keys (2 mt x 8 nt tiles)
        float sa[2][8][4];
        #pragma unroll
        for (int mt = 0; mt < 2; mt++)
            #pragma unroll
            for (int nt = 0; nt < 8; nt++)
                #pragma unroll
                for (int i = 0; i < 4; i++) sa[mt][nt][i] = 0.f;
        #pragma unroll
        for (int kk = 0; kk < 4; kk++) {
            #pragma unroll
            for (int p = 0; p < 4; p++) {
                uint32_t b[4];
                ldm4(b, kbs + (uint32_t)((((p * 16 + krow) * FPAD)
                                          + kcol + kk * 16) * 2));
                #pragma unroll
                for (int mt = 0; mt < 2; mt++) {
                    mma16(sa[mt][2*p],   qf[mt][kk][0], qf[mt][kk][1],
                          qf[mt][kk][2], qf[mt][kk][3], b[0], b[1]);
                    mma16(sa[mt][2*p+1], qf[mt][kk][0], qf[mt][kk][1],
                          qf[mt][kk][2], qf[mt][kk][3], b[2], b[3]);
                }
            }
        }

        // Static softmax: P = exp(S) in fp16 (Q pre-scaled); sums of the
        // fp16-rounded P so numerator/denominator stay consistent.
        uint32_t pf[2][8][2];
        #pragma unroll
        for (int mt = 0; mt < 2; mt++) {
            float s0 = 0.f, s1 = 0.f;
            #pragma unroll
            for (int nt = 0; nt < 8; nt++) {
                __half2 h01 = __floats2half2_rn(__expf(sa[mt][nt][0]), __expf(sa[mt][nt][1]));
                __half2 h23 = __floats2half2_rn(__expf(sa[mt][nt][2]), __expf(sa[mt][nt][3]));
                pf[mt][nt][0] = h2u(h01);
                pf[mt][nt][1] = h2u(h23);
                float2 f01 = __half22float2(h01);
                float2 f23 = __half22float2(h23);
                s0 += f01.x + f01.y;
                s1 += f23.x + f23.y;
            }
            s0 += __shfl_xor_sync(0xffffffffu, s0, 1);
            s0 += __shfl_xor_sync(0xffffffffu, s0, 2);
            s1 += __shfl_xor_sync(0xffffffffu, s1, 1);
            s1 += __shfl_xor_sync(0xffffffffu, s1, 2);
            lsum[mt][0] += s0;
            lsum[mt][1] += s1;
        }

        // PV: O(32q x 64d) += P(32q x 64key) @ V(64key x 64d)
        #pragma unroll
        for (int j = 0; j < 4; j++) {
            #pragma unroll
            for (int p = 0; p < 4; p++) {
                uint32_t b[4];
                ldm4t(b, vbs + (uint32_t)((((j * 16 + vrow) * FPAD)
                                           + p * 16 + vcol) * 2));
                #pragma unroll
                for (int mt = 0; mt < 2; mt++) {
                    mma16(oacc[mt][2*p],   pf[mt][2*j][0], pf[mt][2*j][1],
                          pf[mt][2*j+1][0], pf[mt][2*j+1][1], b[0], b[1]);
                    mma16(oacc[mt][2*p+1], pf[mt][2*j][0], pf[mt][2*j][1],
                          pf[mt][2*j+1][0], pf[mt][2*j+1][1], b[2], b[3]);
                }
            }
        }

        if (c < NC - 1) {
            if (c < NC - 2) { CP_WAIT(1); } else { CP_WAIT(0); }
            __syncthreads();
        }
    }

    // Write out (half)
    #pragma unroll
    for (int mt = 0; mt < 2; mt++) {
        float i0 = 1.f / lsum[mt][0];
        float i1 = 1.f / lsum[mt][1];
        size_t rbase0 = ((size_t)(bb * SEQ + q0 + wid * 32 + mt * 16 + g))     * DIMX + h * HDIM;
        size_t rbase1 = ((size_t)(bb * SEQ + q0 + wid * 32 + mt * 16 + g + 8)) * DIMX + h * HDIM;
        #pragma unroll
        for (int nt = 0; nt < 8; nt++) {
            int d = nt * 8 + 2 * t4;
            *reinterpret_cast<__half2*>(Out + rbase0 + d) =
                __floats2half2_rn(oacc[mt][nt][0] * i0, oacc[mt][nt][1] * i0);
            *reinterpret_cast<__half2*>(Out + rbase1 + d) =
                __floats2half2_rn(oacc[mt][nt][2] * i1, oacc[mt][nt][3] * i1);
        }
    }
}

// ---------------------------------------------------------------------------
// Launch
// ---------------------------------------------------------------------------
extern "C" void kernel_launch(void* const* d_in, const int* in_sizes, int n_in,
                              void* d_out, int out_size)
{
    const float* q  = (const float*)d_in[0];
    const float* k  = (const float*)d_in[1];
    const float* v  = (const float*)d_in[2];
    const float* Wq = (const float*)d_in[3];
    const float* bq = (const float*)d_in[4];
    const float* Wk = (const float*)d_in[5];
    const float* bk = (const float*)d_in[6];
    const float* Wv = (const float*)d_in[7];
    const float* bv = (const float*)d_in[8];
    const float* Wo = (const float*)d_in[9];
    const float* bo = (const float*)d_in[10];
    float* out = (float*)d_out;

    __half *qh, *kh, *vh, *Wh, *pQ, *pK, *pV, *pA;
    float2* rope;
    cudaGetSymbolAddress((void**)&qh, g_qh);
    cudaGetSymbolAddress((void**)&kh, g_kh);
    cudaGetSymbolAddress((void**)&vh, g_vh);
    cudaGetSymbolAddress((void**)&Wh, g_Wh);
    cudaGetSymbolAddress((void**)&pQ, g_Q);
    cudaGetSymbolAddress((void**)&pK, g_K);
    cudaGetSymbolAddress((void**)&pV, g_V);
    cudaGetSymbolAddress((void**)&pA, g_A);
    cudaGetSymbolAddress((void**)&rope, g_rope);

    cudaFuncSetAttribute(proj_h,  cudaFuncAttributeMaxDynamicSharedMemorySize, GSMEM_B);
    cudaFuncSetAttribute(gemmo_h, cudaFuncAttributeMaxDynamicSharedMemorySize, GSMEM_B);
    cudaFuncSetAttribute(flash_h, cudaFuncAttributeMaxDynamicSharedMemorySize, FSMEM_B);

    // staging: fp16 copies + RoPE table
    cvt3<<<dim3(MROWS*DIMX/4/256, 3), 256>>>(q, k, v, qh, kh, vh, MROWS*DIMX/4);
    cvt4<<<dim3(DIMX*DIMX/4/256, 4), 256>>>(Wq, Wk, Wv, Wo, Wh, DIMX*DIMX/4);
    ropetab<<<SEQ*(ROT/2)/256, 256>>>(rope);

    proj_h<<<dim3(DIMX/128, MROWS/128, 3), 128, GSMEM_B>>>(
        qh, kh, vh, Wh, bq, bk, bv, rope, pQ, pK, pV);

    flash_h<<<dim3(SEQ/128, NHEADS, BATCH), 128, FSMEM_B>>>(pQ, pK, pV, pA);

    gemmo_h<<<dim3(DIMX/128, MROWS/128), 128, GSMEM_B>>>(
        pA, Wh + 3*DIMX*DIMX, bo, out);
}